// round 14
// baseline (speedup 1.0000x reference)
#include <cuda_runtime.h>
#include <cstdint>

#define BB 256
#define NN 64

typedef unsigned long long ull;

// ---------- scratch ----------
__device__ float g_scale[48], g_shift[48];
__device__ float g_xnT [BB*NN*48];     // (b,n,p)
__device__ float g_Ar  [BB*NN*256];    // (b,n,h1) includes fr1_b
__device__ float g_As  [BB*NN*256];    // (b,n,h1)
__device__ float g_EbarP[(size_t)BB*NN*128]; // (pair, half, e) partial sums
__device__ float g_Nsum[BB*64];
__device__ float g_n1T [112*256];
__device__ float g_n2T [256*128];
__device__ float g_n3T [128*64];
__device__ uint32_t g_w2h[16384], g_w2l[16384];   // [128 n][128 kpair] bf16x2
__device__ uint32_t g_w3h[4096],  g_w3l[4096];    // [64 e][64 kpair]

__device__ __forceinline__ ull pk2(float x){ull r;asm("mov.b64 %0,{%1,%1};":"=l"(r):"f"(x));return r;}
__device__ __forceinline__ void ff2(ull&d,ull a,ull b){asm("fma.rn.f32x2 %0,%1,%2,%0;":"+l"(d):"l"(a),"l"(b));}
__device__ __forceinline__ float2 up2(ull v){float2 f;asm("mov.b64 {%0,%1},%2;":"=f"(f.x),"=f"(f.y):"l"(v));return f;}

__device__ __forceinline__ uint32_t smem_u32(const void* p){
  uint32_t a;asm("{ .reg .u64 t; cvta.to.shared.u64 t, %1; cvt.u32.u64 %0, t; }":"=r"(a):"l"(p));return a;
}
__device__ __forceinline__ void split2(float a,float b,uint32_t&hp,uint32_t&lp){
  uint32_t h;asm("cvt.rn.bf16x2.f32 %0, %1, %2;":"=r"(h):"f"(b),"f"(a));
  float ra=__uint_as_float(h<<16);
  float rb=__uint_as_float(h&0xFFFF0000u);
  float la=a-ra, lb=b-rb;
  uint32_t l;asm("cvt.rn.bf16x2.f32 %0, %1, %2;":"=r"(l):"f"(lb),"f"(la));
  hp=h;lp=l;
}
#define LDSM4(r0,r1,r2,r3,addr) \
  asm volatile("ldmatrix.sync.aligned.m8n8.x4.shared.b16 {%0,%1,%2,%3}, [%4];" \
    :"=r"(r0),"=r"(r1),"=r"(r2),"=r"(r3):"r"(addr))
__device__ __forceinline__ void mma_bf16(float* d,const uint32_t* a,const uint32_t* b){
  asm volatile("mma.sync.aligned.m16n8k16.row.col.f32.bf16.bf16.f32 "
    "{%0,%1,%2,%3},{%4,%5,%6,%7},{%8,%9},{%0,%1,%2,%3};"
    :"+f"(d[0]),"+f"(d[1]),"+f"(d[2]),"+f"(d[3])
    :"r"(a[0]),"r"(a[1]),"r"(a[2]),"r"(a[3]),"r"(b[0]),"r"(b[1]));
}
// A-operand ldmatrix address (row-major m16k16 tile), XOR-swizzled pitch P bytes
__device__ __forceinline__ uint32_t a_addr(uint32_t base,int row0,int k0,int P,int lane){
  int g=lane&7,sub=lane>>3;
  int row=row0+g+((sub&1)<<3);
  int kb=(k0+((sub>>1)<<3))*2;
  return base + row*P + (((kb>>4)^(row&7))<<4);
}
// B-operand (weights [n][k] row-major; x4 covers 2 n8k16 tiles)
__device__ __forceinline__ uint32_t b_addr(uint32_t base,int n0,int k0,int P,int lane){
  int g=lane&7,sub=lane>>3;
  int n=n0+g+((sub>>1)<<3);
  int kb=(k0+((sub&1)<<3))*2;
  return base + n*P + (((kb>>4)^(n&7))<<4);
}
#define BARG() asm volatile("bar.sync %0, 128;"::"r"(wm+1):"memory")

// k_edge smem layout (bytes)
#define O_W2H 0
#define O_W2L 65536
#define O_W3H 131072
#define O_W3L 147456
#define O_Z   163840   // 4 groups x 16KB (2 chunk bufs of 8KB; H2 hi/lo alias)
#define O_B2  229376
#define O_B3  229888
#define SME_BYTES 230144

// ---------- K1: BN statistics ----------
__global__ void k_bn(const float* __restrict__ x,const float* __restrict__ gam,
                     const float* __restrict__ bet){
  int p=blockIdx.x,t=threadIdx.x;
  float s=0.f,q=0.f;
  for(int i=t;i<BB*NN;i+=256){
    float v=x[(i>>6)*3072+p*64+(i&63)];
    s+=v;q+=v*v;
  }
  __shared__ float rs[256],rq[256];
  rs[t]=s;rq[t]=q;__syncthreads();
  for(int o=128;o>0;o>>=1){if(t<o){rs[t]+=rs[t+o];rq[t]+=rq[t+o];}__syncthreads();}
  if(t==0){
    float m=rs[0]*(1.f/16384.f);
    float var=rq[0]*(1.f/16384.f)-m*m;
    float sc=gam[p]*rsqrtf(var+1e-5f);
    g_scale[p]=sc;g_shift[p]=bet[p]-m*sc;
  }
}

// ---------- K2: weight prep ----------
__global__ void k_wt(const float* __restrict__ w1,const float* __restrict__ w2,
                     const float* __restrict__ w3,const float* __restrict__ fr2w,
                     const float* __restrict__ fr3w){
  int i=blockIdx.x*256+threadIdx.x;
  if(i<28672){int k=i>>8,h=i&255;g_n1T[i]=w1[h*112+k];}
  else if(i<61440){int j=i-28672,k=j>>7,h=j&127;g_n2T[j]=w2[h*256+k];}
  else if(i<69632){int j=i-61440,k=j>>6,e=j&63;g_n3T[j]=w3[e*128+k];}
  else if(i<86016){
    int j=i-69632,n=j>>7,cp=j&127;
    uint32_t h,l;split2(fr2w[n*256+2*cp],fr2w[n*256+2*cp+1],h,l);
    g_w2h[j]=h;g_w2l[j]=l;
  }else if(i<90112){
    int j=i-86016,e=j>>6,cp=j&63;
    uint32_t h,l;split2(fr3w[e*128+2*cp],fr3w[e*128+2*cp+1],h,l);
    g_w3h[j]=h;g_w3l[j]=l;
  }
}

// ---------- K3: xn + per-node edge pre-GEMM Ar(+b1)/As ----------
__global__ __launch_bounds__(256,1) void k_prep(const float* __restrict__ x,
                                                const float* __restrict__ w1,
                                                const float* __restrict__ b1){
  extern __shared__ float sm[];
  float* W=sm;          // [256][97]
  float* xs=W+256*97;   // [64][48]
  int t=threadIdx.x,b=blockIdx.x;
  for(int i=t;i<256*96;i+=256){int o=i/96,k=i-o*96;W[o*97+k]=w1[i];}
  for(int i=t;i<48*64;i+=256){
    int p=i>>6,n=i&63;
    float v=x[b*3072+i]*g_scale[p]+g_shift[p];
    xs[n*48+p]=v;
    g_xnT[(b*64+n)*48+p]=v;
  }
  __syncthreads();
  int o=t;
  float bb=b1[o];
  for(int nt=0;nt<64;nt+=16){
    float aR[16],aS[16];
    #pragma unroll
    for(int j=0;j<16;j++){aR[j]=bb;aS[j]=0.f;}
    for(int p=0;p<48;p++){
      float wr=W[o*97+p],ws=W[o*97+48+p];
      #pragma unroll
      for(int j=0;j<16;j++){
        float xv=xs[(nt+j)*48+p];
        aR[j]=fmaf(wr,xv,aR[j]);aS[j]=fmaf(ws,xv,aS[j]);
      }
    }
    #pragma unroll
    for(int j=0;j<16;j++){
      g_Ar[(b*64+nt+j)*256+o]=aR[j];
      g_As[(b*64+nt+j)*256+o]=aS[j];
    }
  }
}

// ---------- K4: edge MLP via mma.sync bf16 split, 16 warps ----------
// wm = w>>2: each SMSP hosts one warp of each group (R13 win).
// Fill for chunk c+1 is interleaved into chunk c's ks loop (2 of 8 sub-fills
// per ks) so fill LDG latency + STS issue hide under MMA.
__global__ __launch_bounds__(512,1) void k_edge(const float* __restrict__ b2,
                                                const float* __restrict__ b3){
  extern __shared__ char smc[];
  uint32_t sb=smem_u32(smc);
  float* b2s=(float*)(smc+O_B2);
  float* b3s=(float*)(smc+O_B3);
  int t=threadIdx.x,lane=t&31,w=t>>5;
  int wm=w>>2,wn=w&3;           // wm: row group (32 rows), wn: col group
  int gt=wn*32+lane;            // 0..127 within wm group
  int g=lane>>2,tt=lane&3;
  // stage W2/W3 hi+lo into swizzled smem
  for(int i=t;i<16384;i+=512){
    int n=i>>7,cp=i&127;
    uint32_t off=n*512u+(((cp>>2)^(n&7))<<4)+((cp&3)<<2);
    *(uint32_t*)(smc+O_W2H+off)=g_w2h[i];
    *(uint32_t*)(smc+O_W2L+off)=g_w2l[i];
  }
  for(int i=t;i<4096;i+=512){
    int e=i>>6,cp=i&63;
    uint32_t off=e*256u+(((cp>>2)^(e&7))<<4)+((cp&3)<<2);
    *(uint32_t*)(smc+O_W3H+off)=g_w3h[i];
    *(uint32_t*)(smc+O_W3L+off)=g_w3l[i];
  }
  if(t<128)b2s[t]=b2[t];
  if(t>=128&&t<192)b3s[t-128]=b3[t-128];
  __syncthreads();

  char* zgrp=smc+O_Z+wm*16384;
  uint32_t zgrp_u=sb+O_Z+wm*16384;

  for(int base=blockIdx.x*2;base<BB*NN;base+=2*gridDim.x){
    int b=base>>6;
    const float* ArB=g_Ar+(size_t)base*256;
    const float* AsB=g_As+(size_t)b*16384;
    float acc[2][4][4];
    #pragma unroll
    for(int m=0;m<2;m++)
      #pragma unroll
      for(int n=0;n<4;n++){acc[m][n][0]=0.f;acc[m][n][1]=0.f;acc[m][n][2]=0.f;acc[m][n][3]=0.f;}

    // fill 2 jj sub-slices (j0, j0+1) of chunk c into buf d
    #define FILL2(c,d,j0) do{ \
      char* zh=zgrp+(d)*8192; char* zl=zh+4096; \
      _Pragma("unroll") \
      for(int jj=(j0);jj<(j0)+2;jj++){ \
        int idx=gt+(jj<<7); \
        int rl=idx>>5,cp=idx&31; \
        int row=wm*32+rl; \
        int k=((c)<<6)+(cp<<1); \
        int ph=row>>6,s=row&63; \
        float2 ar=*(const float2*)(ArB+ph*256+k); \
        float2 as=*(const float2*)(AsB+s*256+k); \
        uint32_t h,l;split2(fmaxf(ar.x+as.x,0.f),fmaxf(ar.y+as.y,0.f),h,l); \
        uint32_t off=rl*128u+(((cp>>2)^(rl&7))<<4)+((cp&3)<<2); \
        *(uint32_t*)(zh+off)=h;*(uint32_t*)(zl+off)=l; \
      } \
    }while(0)

    FILL2(0,0,0);FILL2(0,0,2);FILL2(0,0,4);FILL2(0,0,6);
    BARG();
    #pragma unroll 1
    for(int c=0;c<4;c++){
      uint32_t zb=zgrp_u+(c&1)*8192;
      #pragma unroll 1
      for(int ks=0;ks<4;ks++){
        int kg=(c<<6)+(ks<<4);
        uint32_t bh[4][2],bl[4][2];
        #pragma unroll
        for(int p=0;p<2;p++){
          uint32_t r0,r1,r2,r3;
          LDSM4(r0,r1,r2,r3,b_addr(sb+O_W2H,wn*32+p*16,kg,512,lane));
          bh[2*p][0]=r0;bh[2*p][1]=r1;bh[2*p+1][0]=r2;bh[2*p+1][1]=r3;
          LDSM4(r0,r1,r2,r3,b_addr(sb+O_W2L,wn*32+p*16,kg,512,lane));
          bl[2*p][0]=r0;bl[2*p][1]=r1;bl[2*p+1][0]=r2;bl[2*p+1][1]=r3;
        }
        uint32_t ah[2][4],al[2][4];
        #pragma unroll
        for(int m=0;m<2;m++){
          LDSM4(ah[m][0],ah[m][1],ah[m][2],ah[m][3],a_addr(zb,m*16,ks*16,128,lane));
          LDSM4(al[m][0],al[m][1],al[m][2],al[m][3],a_addr(zb+4096,m*16,ks*16,128,lane));
        }
        #pragma unroll
        for(int m=0;m<2;m++)
          #pragma unroll
          for(int n=0;n<4;n++)mma_bf16(acc[m][n],ah[m],bh[n]);
        #pragma unroll
        for(int m=0;m<2;m++)
          #pragma unroll
          for(int n=0;n<4;n++)mma_bf16(acc[m][n],ah[m],bl[n]);
        #pragma unroll
        for(int m=0;m<2;m++)
          #pragma unroll
          for(int n=0;n<4;n++)mma_bf16(acc[m][n],al[m],bh[n]);
        if(c<3)FILL2(c+1,(c+1)&1,ks*2);
      }
      BARG();
    }
    // ---- epilogue1: acc -> relu(+b2) -> H2 hi/lo (aliases Z region) ----
    #pragma unroll
    for(int m=0;m<2;m++){
      int r0=m*16+g;
      #pragma unroll
      for(int n=0;n<4;n++){
        int c0=wn*32+n*8+tt*2;
        float f0=fmaxf(acc[m][n][0]+b2s[c0],0.f);
        float f1=fmaxf(acc[m][n][1]+b2s[c0+1],0.f);
        float f2=fmaxf(acc[m][n][2]+b2s[c0],0.f);
        float f3=fmaxf(acc[m][n][3]+b2s[c0+1],0.f);
        uint32_t h0,l0,h1,l1;split2(f0,f1,h0,l0);split2(f2,f3,h1,l1);
        uint32_t cb=(uint32_t)(c0<<1);
        int r8=r0+8;
        uint32_t off0=r0*256u+(((cb>>4)^(r0&7))<<4)+(cb&15);
        uint32_t off1=r8*256u+(((cb>>4)^(r8&7))<<4)+(cb&15);
        *(uint32_t*)(zgrp+off0)=h0;*(uint32_t*)(zgrp+8192+off0)=l0;
        *(uint32_t*)(zgrp+off1)=h1;*(uint32_t*)(zgrp+8192+off1)=l1;
      }
    }
    BARG();
    // ---- GEMM3: D3(32x64 per wm) = H2(32x128) * W3^T ----
    float a3[2][2][4];
    #pragma unroll
    for(int m=0;m<2;m++)
      #pragma unroll
      for(int n=0;n<2;n++){a3[m][n][0]=0.f;a3[m][n][1]=0.f;a3[m][n][2]=0.f;a3[m][n][3]=0.f;}
    #pragma unroll 1
    for(int ks=0;ks<8;ks++){
      uint32_t bh[2][2],bl[2][2];
      {
        uint32_t r0,r1,r2,r3;
        LDSM4(r0,r1,r2,r3,b_addr(sb+O_W3H,wn*16,ks*16,256,lane));
        bh[0][0]=r0;bh[0][1]=r1;bh[1][0]=r2;bh[1][1]=r3;
        LDSM4(r0,r1,r2,r3,b_addr(sb+O_W3L,wn*16,ks*16,256,lane));
        bl[0][0]=r0;bl[0][1]=r1;bl[1][0]=r2;bl[1][1]=r3;
      }
      uint32_t ah[2][4],al[2][4];
      #pragma unroll
      for(int m=0;m<2;m++){
        LDSM4(ah[m][0],ah[m][1],ah[m][2],ah[m][3],a_addr(zgrp_u,m*16,ks*16,256,lane));
        LDSM4(al[m][0],al[m][1],al[m][2],al[m][3],a_addr(zgrp_u+8192,m*16,ks*16,256,lane));
      }
      #pragma unroll
      for(int m=0;m<2;m++)
        #pragma unroll
        for(int n=0;n<2;n++){
          mma_bf16(a3[m][n],ah[m],bh[n]);
          mma_bf16(a3[m][n],ah[m],bl[n]);
          mma_bf16(a3[m][n],al[m],bh[n]);
        }
    }
    // ---- epilogue2: relu(+b3), mask s==r, reduce over rows -> global partials ----
    int php=wm>>1;
    {
      int r=(base+php)&63;
      float ps[2][2];
      #pragma unroll
      for(int n=0;n<2;n++){ps[n][0]=0.f;ps[n][1]=0.f;}
      #pragma unroll
      for(int m=0;m<2;m++){
        int row=wm*32+m*16+g;
        float m1=((row&63)!=r)?1.f:0.f;
        float m2=(((row+8)&63)!=r)?1.f:0.f;
        #pragma unroll
        for(int n=0;n<2;n++){
          int c0=wn*16+n*8+tt*2;
          ps[n][0]+=m1*fmaxf(a3[m][n][0]+b3s[c0],0.f)+m2*fmaxf(a3[m][n][2]+b3s[c0],0.f);
          ps[n][1]+=m1*fmaxf(a3[m][n][1]+b3s[c0+1],0.f)+m2*fmaxf(a3[m][n][3]+b3s[c0+1],0.f);
        }
      }
      #pragma unroll
      for(int n=0;n<2;n++)
        #pragma unroll
        for(int q=0;q<2;q++){
          float v=ps[n][q];
          v+=__shfl_xor_sync(0xFFFFFFFFu,v,4);
          v+=__shfl_xor_sync(0xFFFFFFFFu,v,8);
          v+=__shfl_xor_sync(0xFFFFFFFFu,v,16);
          ps[n][q]=v;
        }
      if(g==0){
        float* dst=g_EbarP+((size_t)(base+php)*128+(size_t)(wm&1)*64);
        #pragma unroll
        for(int n=0;n<2;n++){
          int c0=wn*16+n*8+tt*2;
          dst[c0]=ps[n][0];
          dst[c0+1]=ps[n][1];
        }
      }
    }
    BARG();     // zgrp free for next iteration's fill
    #undef FILL2
  }
}

// ---------- K5: node MLP + per-batch sum ----------
__global__ __launch_bounds__(256,1) void k_node(const float* __restrict__ bo1,
    const float* __restrict__ bo2,const float* __restrict__ bo3){
  extern __shared__ float sm[];
  float* CT=sm;             // [112][68]
  float* H1T=CT+112*68;     // [256][68]
  float* H2T=H1T+256*68;    // [128][68]
  float* red=H2T+128*68;    // [16][64]
  float* bs1=red+1024;float* bs2=bs1+256;float* bs3=bs2+128;
  int t=threadIdx.x,b=blockIdx.x;
  int ty=t>>4,tx=t&15,ty4=ty*4,tx8=tx*8,tx4=tx*4,tx16=tx*16;
  bs1[t]=bo1[t];
  if(t<128)bs2[t]=bo2[t];
  if(t<64)bs3[t]=bo3[t];
  for(int i=t;i<64*48;i+=256){int n=i/48,p=i-n*48;CT[p*68+n]=g_xnT[(b*64+n)*48+p];}
  for(int i=t;i<64*64;i+=256){
    int n=i>>6,e=i&63;
    const float* pp=g_EbarP+((size_t)(b*64+n)*128);
    CT[(48+e)*68+n]=pp[e]+pp[64+e];
  }
  __syncthreads();
  { // 112 -> 256
    ull acc[4][8];
    #pragma unroll
    for(int i=0;i<4;i++)
      #pragma unroll
      for(int j=0;j<8;j++)acc[i][j]=0;
    #pragma unroll 4
    for(int k=0;k<112;k++){
      float4 av=*(const float4*)(CT+k*68+ty4);
      const ulonglong2* wp=(const ulonglong2*)(g_n1T+k*256+tx16);
      ulonglong2 w0=wp[0],w1=wp[1],w2=wp[2],w3=wp[3];
      ull a[4]={pk2(av.x),pk2(av.y),pk2(av.z),pk2(av.w)};
      #pragma unroll
      for(int si=0;si<4;si++){
        ff2(acc[si][0],a[si],w0.x);ff2(acc[si][1],a[si],w0.y);
        ff2(acc[si][2],a[si],w1.x);ff2(acc[si][3],a[si],w1.y);
        ff2(acc[si][4],a[si],w2.x);ff2(acc[si][5],a[si],w2.y);
        ff2(acc[si][6],a[si],w3.x);ff2(acc[si][7],a[si],w3.y);
      }
    }
    #pragma unroll
    for(int si=0;si<4;si++){
      int s=ty4+si;
      #pragma unroll
      for(int hp=0;hp<8;hp++){
        float2 f=up2(acc[si][hp]);
        int h=tx16+2*hp;
        H1T[h*68+s]=fmaxf(f.x+bs1[h],0.f);
        H1T[(h+1)*68+s]=fmaxf(f.y+bs1[h+1],0.f);
      }
    }
  }
  __syncthreads();
  { // 256 -> 128
    ull acc[4][4];
    #pragma unroll
    for(int i=0;i<4;i++){acc[i][0]=0;acc[i][1]=0;acc[i][2]=0;acc[i][3]=0;}
    #pragma unroll 4
    for(int k=0;k<256;k++){
      float4 av=*(const float4*)(H1T+k*68+ty4);
      const ulonglong2* wp=(const ulonglong2*)(g_n2T+k*128+tx8);
      ulonglong2 wA=wp[0],wB=wp[1];
      ull a[4]={pk2(av.x),pk2(av.y),pk2(av.z),pk2(av.w)};
      ull wv[4]={wA.x,wA.y,wB.x,wB.y};
      #pragma unroll
      for(int si=0;si<4;si++){
        #pragma unroll
        for(int hj=0;hj<4;hj++)ff2(acc[si][hj],a[si],wv[hj]);
      }
    }
    #pragma unroll
    for(int si=0;si<4;si++){
      int s=ty4+si;
      #pragma unroll
      for(int hp=0;hp<4;hp++){
        float2 f=up2(acc[si][hp]);
        int h=tx8+2*hp;
        H2T[h*68+s]=fmaxf(f.x+bs2[h],0.f);
        H2T[(h+1)*68+s]=fmaxf(f.y+bs2[h+1],0.f);
      }
    }
  }
  __syncthreads();
  { // 128 -> 64 + token sum
    ull acc[4][2];
    #pragma unroll
    for(int i=0;i<4;i++){acc[i][0]=0;acc[i][1]=0;}
    #pragma unroll 4
    for(int k=0;k<128;k++){
      float4 av=*(const float4*)(H2T+k*68+ty4);
      ulonglong2 wv=*(const ulonglong2*)(g_n3T+k*64+tx4);
      ull a[4]={pk2(av.x),pk2(av.y),pk2(av.z),pk2(av.w)};
      #pragma unroll
      for(int si=0;si<4;si++){ff2(acc[si][0],a[si],wv.x);ff2(acc[si][1],a[si],wv.y);}
    }
    float ps[4]={0.f,0.f,0.f,0.f};
    #pragma unroll
    for(int si=0;si<4;si++){
      float2 f0=up2(acc[si][0]),f1=up2(acc[si][1]);
      ps[0]+=fmaxf(f0.x+bs3[tx4],0.f);
      ps[1]+=fmaxf(f0.y+bs3[tx4+1],0.f);
      ps[2]+=fmaxf(f1.x+bs3[tx4+2],0.f);
      ps[3]+=fmaxf(f1.y+bs3[tx4+3],0.f);
    }
    red[ty*64+tx4]=ps[0];red[ty*64+tx4+1]=ps[1];
    red[ty*64+tx4+2]=ps[2];red[ty*64+tx4+3]=ps[3];
    __syncthreads();
    if(t<64){
      float s0=0.f;
      #pragma unroll
      for(int q=0;q<16;q++)s0+=red[q*64+t];
      g_Nsum[b*64+t]=s0;
    }
  }
}

// ---------- K6: FC head ----------
__global__ void k_head(const float* __restrict__ w1,const float* __restrict__ b1,
                       const float* __restrict__ w2,const float* __restrict__ b2,
                       const float* __restrict__ w3,const float* __restrict__ b3,
                       float* __restrict__ out){
  __shared__ float s1[1600],s2[375],s3[75],sb1[25],sb2[15],sb3[5];
  int t=threadIdx.x;
  for(int i=t;i<1600;i+=256)s1[i]=w1[i];
  for(int i=t;i<375;i+=256)s2[i]=w2[i];
  if(t<75)s3[t]=w3[t];
  if(t<25)sb1[t]=b1[t];
  if(t<15)sb2[t]=b2[t];
  if(t<5)sb3[t]=b3[t];
  __syncthreads();
  float a[64];
  #pragma unroll
  for(int j=0;j<64;j++)a[j]=g_Nsum[t*64+j];
  float h1[25];
  for(int o=0;o<25;o++){float v=sb1[o];for(int j=0;j<64;j++)v=fmaf(s1[o*64+j],a[j],v);h1[o]=v;}
  float h2[15];
  for(int o=0;o<15;o++){float v=sb2[o];for(int j=0;j<25;j++)v=fmaf(s2[o*25+j],h1[j],v);h2[o]=v;}
  for(int o=0;o<5;o++){float v=sb3[o];for(int j=0;j<15;j++)v=fmaf(s3[o*15+j],h2[j],v);out[t*5+o]=v;}
}

extern "C" void kernel_launch(void* const* d_in,const int* in_sizes,int n_in,
                              void* d_out,int out_size){
  const float* x   =(const float*)d_in[0];
  const float* gam =(const float*)d_in[3];
  const float* bet =(const float*)d_in[4];
  const float* fr1w=(const float*)d_in[5]; const float* fr1b=(const float*)d_in[6];
  const float* fr2w=(const float*)d_in[7]; const float* fr2b=(const float*)d_in[8];
  const float* fr3w=(const float*)d_in[9]; const float* fr3b=(const float*)d_in[10];
  const float* fo1w=(const float*)d_in[11];const float* fo1b=(const float*)d_in[12];
  const float* fo2w=(const float*)d_in[13];const float* fo2b=(const float*)d_in[14];
  const float* fo3w=(const float*)d_in[15];const float* fo3b=(const float*)d_in[16];
  const float* fc1w=(const float*)d_in[17];const float* fc1b=(const float*)d_in[18];
  const float* fc2w=(const float*)d_in[19];const float* fc2b=(const float*)d_in[20];
  const float* fc3w=(const float*)d_in[21];const float* fc3b=(const float*)d_in[22];
  float* out=(float*)d_out;
  int smP=(256*97+64*48)*4;
  int smN=(112*68+256*68+128*68+1024+256+128+64)*4;
  cudaFuncSetAttribute(k_prep,cudaFuncAttributeMaxDynamicSharedMemorySize,smP);
  cudaFuncSetAttribute(k_edge,cudaFuncAttributeMaxDynamicSharedMemorySize,SME_BYTES);
  cudaFuncSetAttribute(k_node,cudaFuncAttributeMaxDynamicSharedMemorySize,smN);
  k_bn<<<48,256>>>(x,gam,bet);
  k_wt<<<352,256>>>(fo1w,fo2w,fo3w,fr2w,fr3w);
  k_prep<<<256,256,smP>>>(x,fr1w,fr1b);
  k_edge<<<152,512,SME_BYTES>>>(fr2b,fr3b);
  k_node<<<256,256,smN>>>(fo1b,fo2b,fo3b);
  k_head<<<1,256>>>(fc1w,fc1b,fc2w,fc2b,fc3w,fc3b,out);
}

// round 16
// speedup vs baseline: 1.6388x; 1.6388x over previous
#include <cuda_runtime.h>
#include <cstdint>

#define BB 256
#define NN 64

typedef unsigned long long ull;

// ---------- scratch ----------
__device__ float g_scale[48], g_shift[48];
__device__ float g_xnT [BB*NN*48];     // (b,n,p)
__device__ float g_Ar  [BB*NN*256];    // (b,n,h1) includes fr1_b
__device__ float g_As  [BB*NN*256];    // (b,n,h1)
__device__ float g_EbarP[(size_t)BB*NN*128]; // (pair, half, e) partial sums
__device__ float g_Nsum[BB*64];
__device__ float g_n1T [112*256];
__device__ float g_n2T [256*128];
__device__ float g_n3T [128*64];
__device__ uint32_t g_w2h[16384], g_w2l[16384];   // [128 n][128 kpair] bf16x2
__device__ uint32_t g_w3h[4096],  g_w3l[4096];    // [64 e][64 kpair]

__device__ __forceinline__ ull pk2(float x){ull r;asm("mov.b64 %0,{%1,%1};":"=l"(r):"f"(x));return r;}
__device__ __forceinline__ void ff2(ull&d,ull a,ull b){asm("fma.rn.f32x2 %0,%1,%2,%0;":"+l"(d):"l"(a),"l"(b));}
__device__ __forceinline__ float2 up2(ull v){float2 f;asm("mov.b64 {%0,%1},%2;":"=f"(f.x),"=f"(f.y):"l"(v));return f;}

__device__ __forceinline__ uint32_t smem_u32(const void* p){
  uint32_t a;asm("{ .reg .u64 t; cvta.to.shared.u64 t, %1; cvt.u32.u64 %0, t; }":"=r"(a):"l"(p));return a;
}
__device__ __forceinline__ void split2(float a,float b,uint32_t&hp,uint32_t&lp){
  uint32_t h;asm("cvt.rn.bf16x2.f32 %0, %1, %2;":"=r"(h):"f"(b),"f"(a));
  float ra=__uint_as_float(h<<16);
  float rb=__uint_as_float(h&0xFFFF0000u);
  float la=a-ra, lb=b-rb;
  uint32_t l;asm("cvt.rn.bf16x2.f32 %0, %1, %2;":"=r"(l):"f"(lb),"f"(la));
  hp=h;lp=l;
}
#define LDSM4(r0,r1,r2,r3,addr) \
  asm volatile("ldmatrix.sync.aligned.m8n8.x4.shared.b16 {%0,%1,%2,%3}, [%4];" \
    :"=r"(r0),"=r"(r1),"=r"(r2),"=r"(r3):"r"(addr))
__device__ __forceinline__ void mma_bf16(float* d,const uint32_t* a,const uint32_t* b){
  asm volatile("mma.sync.aligned.m16n8k16.row.col.f32.bf16.bf16.f32 "
    "{%0,%1,%2,%3},{%4,%5,%6,%7},{%8,%9},{%0,%1,%2,%3};"
    :"+f"(d[0]),"+f"(d[1]),"+f"(d[2]),"+f"(d[3])
    :"r"(a[0]),"r"(a[1]),"r"(a[2]),"r"(a[3]),"r"(b[0]),"r"(b[1]));
}
// A-operand ldmatrix address (row-major m16k16 tile), XOR-swizzled pitch P bytes
__device__ __forceinline__ uint32_t a_addr(uint32_t base,int row0,int k0,int P,int lane){
  int g=lane&7,sub=lane>>3;
  int row=row0+g+((sub&1)<<3);
  int kb=(k0+((sub>>1)<<3))*2;
  return base + row*P + (((kb>>4)^(row&7))<<4);
}
// B-operand (weights [n][k] row-major; x4 covers 2 n8k16 tiles)
__device__ __forceinline__ uint32_t b_addr(uint32_t base,int n0,int k0,int P,int lane){
  int g=lane&7,sub=lane>>3;
  int n=n0+g+((sub>>1)<<3);
  int kb=(k0+((sub&1)<<3))*2;
  return base + n*P + (((kb>>4)^(n&7))<<4);
}
#define BARG() asm volatile("bar.sync %0, 128;"::"r"(wm+1):"memory")

// k_edge smem layout (bytes)
#define O_W2H 0
#define O_W2L 65536
#define O_W3H 131072
#define O_W3L 147456
#define O_Z   163840   // 4 groups x 16KB (2 chunk bufs of 8KB; H2 hi/lo alias)
#define O_B2  229376
#define O_B3  229888
#define SME_BYTES 230144

// ---------- K1: BN statistics ----------
__global__ void k_bn(const float* __restrict__ x,const float* __restrict__ gam,
                     const float* __restrict__ bet){
  int p=blockIdx.x,t=threadIdx.x;
  float s=0.f,q=0.f;
  for(int i=t;i<BB*NN;i+=256){
    float v=x[(i>>6)*3072+p*64+(i&63)];
    s+=v;q+=v*v;
  }
  __shared__ float rs[256],rq[256];
  rs[t]=s;rq[t]=q;__syncthreads();
  for(int o=128;o>0;o>>=1){if(t<o){rs[t]+=rs[t+o];rq[t]+=rq[t+o];}__syncthreads();}
  if(t==0){
    float m=rs[0]*(1.f/16384.f);
    float var=rq[0]*(1.f/16384.f)-m*m;
    float sc=gam[p]*rsqrtf(var+1e-5f);
    g_scale[p]=sc;g_shift[p]=bet[p]-m*sc;
  }
}

// ---------- K2: weight prep ----------
__global__ void k_wt(const float* __restrict__ w1,const float* __restrict__ w2,
                     const float* __restrict__ w3,const float* __restrict__ fr2w,
                     const float* __restrict__ fr3w){
  int i=blockIdx.x*256+threadIdx.x;
  if(i<28672){int k=i>>8,h=i&255;g_n1T[i]=w1[h*112+k];}
  else if(i<61440){int j=i-28672,k=j>>7,h=j&127;g_n2T[j]=w2[h*256+k];}
  else if(i<69632){int j=i-61440,k=j>>6,e=j&63;g_n3T[j]=w3[e*128+k];}
  else if(i<86016){
    int j=i-69632,n=j>>7,cp=j&127;
    uint32_t h,l;split2(fr2w[n*256+2*cp],fr2w[n*256+2*cp+1],h,l);
    g_w2h[j]=h;g_w2l[j]=l;
  }else if(i<90112){
    int j=i-86016,e=j>>6,cp=j&63;
    uint32_t h,l;split2(fr3w[e*128+2*cp],fr3w[e*128+2*cp+1],h,l);
    g_w3h[j]=h;g_w3l[j]=l;
  }
}

// ---------- K3: xn + per-node edge pre-GEMM Ar(+b1)/As ----------
__global__ __launch_bounds__(256,1) void k_prep(const float* __restrict__ x,
                                                const float* __restrict__ w1,
                                                const float* __restrict__ b1){
  extern __shared__ float sm[];
  float* W=sm;          // [256][97]
  float* xs=W+256*97;   // [64][48]
  int t=threadIdx.x,b=blockIdx.x;
  for(int i=t;i<256*96;i+=256){int o=i/96,k=i-o*96;W[o*97+k]=w1[i];}
  for(int i=t;i<48*64;i+=256){
    int p=i>>6,n=i&63;
    float v=x[b*3072+i]*g_scale[p]+g_shift[p];
    xs[n*48+p]=v;
    g_xnT[(b*64+n)*48+p]=v;
  }
  __syncthreads();
  int o=t;
  float bb=b1[o];
  for(int nt=0;nt<64;nt+=16){
    float aR[16],aS[16];
    #pragma unroll
    for(int j=0;j<16;j++){aR[j]=bb;aS[j]=0.f;}
    for(int p=0;p<48;p++){
      float wr=W[o*97+p],ws=W[o*97+48+p];
      #pragma unroll
      for(int j=0;j<16;j++){
        float xv=xs[(nt+j)*48+p];
        aR[j]=fmaf(wr,xv,aR[j]);aS[j]=fmaf(ws,xv,aS[j]);
      }
    }
    #pragma unroll
    for(int j=0;j<16;j++){
      g_Ar[(b*64+nt+j)*256+o]=aR[j];
      g_As[(b*64+nt+j)*256+o]=aS[j];
    }
  }
}

// ---------- K4: edge MLP via mma.sync bf16 split, 16 warps ----------
// wm = w>>2: each SMSP hosts one warp of each group (R13 win).
// Fill of chunk c+1 pipelined: prefetch LDGs before chunk c's ks loop,
// consume (split+STS) at ks==1 and after the loop. cp=gt&31 is jj-invariant
// so ar is a single float2 per chunk; per-jj state is just as (float2).
__global__ __launch_bounds__(512,1) void k_edge(const float* __restrict__ b2,
                                                const float* __restrict__ b3){
  extern __shared__ char smc[];
  uint32_t sb=smem_u32(smc);
  float* b2s=(float*)(smc+O_B2);
  float* b3s=(float*)(smc+O_B3);
  int t=threadIdx.x,lane=t&31,w=t>>5;
  int wm=w>>2,wn=w&3;           // wm: row group (32 rows), wn: col group
  int gt=wn*32+lane;            // 0..127 within wm group
  int g=lane>>2,tt=lane&3;
  // stage W2/W3 hi+lo into swizzled smem
  for(int i=t;i<16384;i+=512){
    int n=i>>7,cp=i&127;
    uint32_t off=n*512u+(((cp>>2)^(n&7))<<4)+((cp&3)<<2);
    *(uint32_t*)(smc+O_W2H+off)=g_w2h[i];
    *(uint32_t*)(smc+O_W2L+off)=g_w2l[i];
  }
  for(int i=t;i<4096;i+=512){
    int e=i>>6,cp=i&63;
    uint32_t off=e*256u+(((cp>>2)^(e&7))<<4)+((cp&3)<<2);
    *(uint32_t*)(smc+O_W3H+off)=g_w3h[i];
    *(uint32_t*)(smc+O_W3L+off)=g_w3l[i];
  }
  if(t<128)b2s[t]=b2[t];
  if(t>=128&&t<192)b3s[t-128]=b3[t-128];
  __syncthreads();

  char* zgrp=smc+O_Z+wm*16384;
  uint32_t zgrp_u=sb+O_Z+wm*16384;

  // fill-pipe invariants
  int cpF=gt&31;                 // jj-invariant k pair index
  int rlb=gt>>5;                 // jj row base (rl = rlb + 4*jj)
  int phF=wm>>1;                 // jj-invariant Ar row

  for(int base=blockIdx.x*2;base<BB*NN;base+=2*gridDim.x){
    int b=base>>6;
    const float* ArB=g_Ar+(size_t)base*256;
    const float* AsB=g_As+(size_t)b*16384;
    float acc[2][4][4];
    #pragma unroll
    for(int m=0;m<2;m++)
      #pragma unroll
      for(int n=0;n<4;n++){acc[m][n][0]=0.f;acc[m][n][1]=0.f;acc[m][n][2]=0.f;acc[m][n][3]=0.f;}

    // full fill of chunk c into buf d (used for chunk 0 only)
    #define FILLZ(c,d) do{ \
      char* zh=zgrp+(d)*8192; char* zl=zh+4096; \
      int kk=((c)<<6)+(cpF<<1); \
      float2 arv=*(const float2*)(ArB+phF*256+kk); \
      _Pragma("unroll") \
      for(int jj=0;jj<8;jj++){ \
        int rl=rlb+(jj<<2); \
        int s=(wm*32+rl)&63; \
        float2 as=*(const float2*)(AsB+s*256+kk); \
        uint32_t h,l;split2(fmaxf(arv.x+as.x,0.f),fmaxf(arv.y+as.y,0.f),h,l); \
        uint32_t off=rl*128u+(((cpF>>2)^(rl&7))<<4)+((cpF&3)<<2); \
        *(uint32_t*)(zh+off)=h;*(uint32_t*)(zl+off)=l; \
      } \
    }while(0)
    // consume 4 prefetched as values (jj = j0..j0+3) into buf d
    #define CONSUME4(d,j0) do{ \
      char* zh=zgrp+(d)*8192; char* zl=zh+4096; \
      _Pragma("unroll") \
      for(int j=0;j<4;j++){ \
        int rl=rlb+(((j0)+j)<<2); \
        uint32_t h,l;split2(fmaxf(arP.x+asP[j].x,0.f),fmaxf(arP.y+asP[j].y,0.f),h,l); \
        uint32_t off=rl*128u+(((cpF>>2)^(rl&7))<<4)+((cpF&3)<<2); \
        *(uint32_t*)(zh+off)=h;*(uint32_t*)(zl+off)=l; \
      } \
    }while(0)
    // prefetch 4 as values for chunk cc, jj=j0..j0+3
    #define PREF4(cc,j0) do{ \
      int kk=((cc)<<6)+(cpF<<1); \
      _Pragma("unroll") \
      for(int j=0;j<4;j++){ \
        int rl=rlb+(((j0)+j)<<2); \
        int s=(wm*32+rl)&63; \
        asP[j]=*(const float2*)(AsB+s*256+kk); \
      } \
    }while(0)

    FILLZ(0,0);
    BARG();
    float2 arP; float2 asP[4];
    #pragma unroll 1
    for(int c=0;c<4;c++){
      uint32_t zb=zgrp_u+(c&1)*8192;
      if(c<3){
        int kk=((c+1)<<6)+(cpF<<1);
        arP=*(const float2*)(ArB+phF*256+kk);
        PREF4(c+1,0);
      }
      #pragma unroll 1
      for(int ks=0;ks<4;ks++){
        int kg=(c<<6)+(ks<<4);
        uint32_t bh[4][2],bl[4][2];
        #pragma unroll
        for(int p=0;p<2;p++){
          uint32_t r0,r1,r2,r3;
          LDSM4(r0,r1,r2,r3,b_addr(sb+O_W2H,wn*32+p*16,kg,512,lane));
          bh[2*p][0]=r0;bh[2*p][1]=r1;bh[2*p+1][0]=r2;bh[2*p+1][1]=r3;
          LDSM4(r0,r1,r2,r3,b_addr(sb+O_W2L,wn*32+p*16,kg,512,lane));
          bl[2*p][0]=r0;bl[2*p][1]=r1;bl[2*p+1][0]=r2;bl[2*p+1][1]=r3;
        }
        uint32_t ah[2][4],al[2][4];
        #pragma unroll
        for(int m=0;m<2;m++){
          LDSM4(ah[m][0],ah[m][1],ah[m][2],ah[m][3],a_addr(zb,m*16,ks*16,128,lane));
          LDSM4(al[m][0],al[m][1],al[m][2],al[m][3],a_addr(zb+4096,m*16,ks*16,128,lane));
        }
        #pragma unroll
        for(int m=0;m<2;m++)
          #pragma unroll
          for(int n=0;n<4;n++)mma_bf16(acc[m][n],ah[m],bh[n]);
        #pragma unroll
        for(int m=0;m<2;m++)
          #pragma unroll
          for(int n=0;n<4;n++)mma_bf16(acc[m][n],ah[m],bl[n]);
        #pragma unroll
        for(int m=0;m<2;m++)
          #pragma unroll
          for(int n=0;n<4;n++)mma_bf16(acc[m][n],al[m],bh[n]);
        if(c<3&&ks==1){
          CONSUME4((c+1)&1,0);   // split+STS for jj0..3 (loads long since landed)
          PREF4(c+1,4);          // start loads for jj4..7
        }
      }
      if(c<3)CONSUME4((c+1)&1,4);
      BARG();
    }
    // ---- epilogue1: acc -> relu(+b2) -> H2 hi/lo (aliases Z region) ----
    #pragma unroll
    for(int m=0;m<2;m++){
      int r0=m*16+g;
      #pragma unroll
      for(int n=0;n<4;n++){
        int c0=wn*32+n*8+tt*2;
        float f0=fmaxf(acc[m][n][0]+b2s[c0],0.f);
        float f1=fmaxf(acc[m][n][1]+b2s[c0+1],0.f);
        float f2=fmaxf(acc[m][n][2]+b2s[c0],0.f);
        float f3=fmaxf(acc[m][n][3]+b2s[c0+1],0.f);
        uint32_t h0,l0,h1,l1;split2(f0,f1,h0,l0);split2(f2,f3,h1,l1);
        uint32_t cb=(uint32_t)(c0<<1);
        int r8=r0+8;
        uint32_t off0=r0*256u+(((cb>>4)^(r0&7))<<4)+(cb&15);
        uint32_t off1=r8*256u+(((cb>>4)^(r8&7))<<4)+(cb&15);
        *(uint32_t*)(zgrp+off0)=h0;*(uint32_t*)(zgrp+8192+off0)=l0;
        *(uint32_t*)(zgrp+off1)=h1;*(uint32_t*)(zgrp+8192+off1)=l1;
      }
    }
    BARG();
    // ---- GEMM3: D3(32x64 per wm) = H2(32x128) * W3^T ----
    float a3[2][2][4];
    #pragma unroll
    for(int m=0;m<2;m++)
      #pragma unroll
      for(int n=0;n<2;n++){a3[m][n][0]=0.f;a3[m][n][1]=0.f;a3[m][n][2]=0.f;a3[m][n][3]=0.f;}
    #pragma unroll 1
    for(int ks=0;ks<8;ks++){
      uint32_t bh[2][2],bl[2][2];
      {
        uint32_t r0,r1,r2,r3;
        LDSM4(r0,r1,r2,r3,b_addr(sb+O_W3H,wn*16,ks*16,256,lane));
        bh[0][0]=r0;bh[0][1]=r1;bh[1][0]=r2;bh[1][1]=r3;
        LDSM4(r0,r1,r2,r3,b_addr(sb+O_W3L,wn*16,ks*16,256,lane));
        bl[0][0]=r0;bl[0][1]=r1;bl[1][0]=r2;bl[1][1]=r3;
      }
      uint32_t ah[2][4],al[2][4];
      #pragma unroll
      for(int m=0;m<2;m++){
        LDSM4(ah[m][0],ah[m][1],ah[m][2],ah[m][3],a_addr(zgrp_u,m*16,ks*16,256,lane));
        LDSM4(al[m][0],al[m][1],al[m][2],al[m][3],a_addr(zgrp_u+8192,m*16,ks*16,256,lane));
      }
      #pragma unroll
      for(int m=0;m<2;m++)
        #pragma unroll
        for(int n=0;n<2;n++){
          mma_bf16(a3[m][n],ah[m],bh[n]);
          mma_bf16(a3[m][n],ah[m],bl[n]);
          mma_bf16(a3[m][n],al[m],bh[n]);
        }
    }
    // ---- epilogue2: relu(+b3), mask s==r, reduce over rows -> global partials ----
    int php=wm>>1;
    {
      int r=(base+php)&63;
      float ps[2][2];
      #pragma unroll
      for(int n=0;n<2;n++){ps[n][0]=0.f;ps[n][1]=0.f;}
      #pragma unroll
      for(int m=0;m<2;m++){
        int row=wm*32+m*16+g;
        float m1=((row&63)!=r)?1.f:0.f;
        float m2=(((row+8)&63)!=r)?1.f:0.f;
        #pragma unroll
        for(int n=0;n<2;n++){
          int c0=wn*16+n*8+tt*2;
          ps[n][0]+=m1*fmaxf(a3[m][n][0]+b3s[c0],0.f)+m2*fmaxf(a3[m][n][2]+b3s[c0],0.f);
          ps[n][1]+=m1*fmaxf(a3[m][n][1]+b3s[c0+1],0.f)+m2*fmaxf(a3[m][n][3]+b3s[c0+1],0.f);
        }
      }
      #pragma unroll
      for(int n=0;n<2;n++)
        #pragma unroll
        for(int q=0;q<2;q++){
          float v=ps[n][q];
          v+=__shfl_xor_sync(0xFFFFFFFFu,v,4);
          v+=__shfl_xor_sync(0xFFFFFFFFu,v,8);
          v+=__shfl_xor_sync(0xFFFFFFFFu,v,16);
          ps[n][q]=v;
        }
      if(g==0){
        float* dst=g_EbarP+((size_t)(base+php)*128+(size_t)(wm&1)*64);
        #pragma unroll
        for(int n=0;n<2;n++){
          int c0=wn*16+n*8+tt*2;
          dst[c0]=ps[n][0];
          dst[c0+1]=ps[n][1];
        }
      }
    }
    BARG();     // zgrp free for next iteration's fill
    #undef FILLZ
    #undef CONSUME4
    #undef PREF4
  }
}

// ---------- K5: node MLP + per-batch sum ----------
__global__ __launch_bounds__(256,1) void k_node(const float* __restrict__ bo1,
    const float* __restrict__ bo2,const float* __restrict__ bo3){
  extern __shared__ float sm[];
  float* CT=sm;             // [112][68]
  float* H1T=CT+112*68;     // [256][68]
  float* H2T=H1T+256*68;    // [128][68]
  float* red=H2T+128*68;    // [16][64]
  float* bs1=red+1024;float* bs2=bs1+256;float* bs3=bs2+128;
  int t=threadIdx.x,b=blockIdx.x;
  int ty=t>>4,tx=t&15,ty4=ty*4,tx8=tx*8,tx4=tx*4,tx16=tx*16;
  bs1[t]=bo1[t];
  if(t<128)bs2[t]=bo2[t];
  if(t<64)bs3[t]=bo3[t];
  for(int i=t;i<64*48;i+=256){int n=i/48,p=i-n*48;CT[p*68+n]=g_xnT[(b*64+n)*48+p];}
  for(int i=t;i<64*64;i+=256){
    int n=i>>6,e=i&63;
    const float* pp=g_EbarP+((size_t)(b*64+n)*128);
    CT[(48+e)*68+n]=pp[e]+pp[64+e];
  }
  __syncthreads();
  { // 112 -> 256
    ull acc[4][8];
    #pragma unroll
    for(int i=0;i<4;i++)
      #pragma unroll
      for(int j=0;j<8;j++)acc[i][j]=0;
    #pragma unroll 4
    for(int k=0;k<112;k++){
      float4 av=*(const float4*)(CT+k*68+ty4);
      const ulonglong2* wp=(const ulonglong2*)(g_n1T+k*256+tx16);
      ulonglong2 w0=wp[0],w1=wp[1],w2=wp[2],w3=wp[3];
      ull a[4]={pk2(av.x),pk2(av.y),pk2(av.z),pk2(av.w)};
      #pragma unroll
      for(int si=0;si<4;si++){
        ff2(acc[si][0],a[si],w0.x);ff2(acc[si][1],a[si],w0.y);
        ff2(acc[si][2],a[si],w1.x);ff2(acc[si][3],a[si],w1.y);
        ff2(acc[si][4],a[si],w2.x);ff2(acc[si][5],a[si],w2.y);
        ff2(acc[si][6],a[si],w3.x);ff2(acc[si][7],a[si],w3.y);
      }
    }
    #pragma unroll
    for(int si=0;si<4;si++){
      int s=ty4+si;
      #pragma unroll
      for(int hp=0;hp<8;hp++){
        float2 f=up2(acc[si][hp]);
        int h=tx16+2*hp;
        H1T[h*68+s]=fmaxf(f.x+bs1[h],0.f);
        H1T[(h+1)*68+s]=fmaxf(f.y+bs1[h+1],0.f);
      }
    }
  }
  __syncthreads();
  { // 256 -> 128
    ull acc[4][4];
    #pragma unroll
    for(int i=0;i<4;i++){acc[i][0]=0;acc[i][1]=0;acc[i][2]=0;acc[i][3]=0;}
    #pragma unroll 4
    for(int k=0;k<256;k++){
      float4 av=*(const float4*)(H1T+k*68+ty4);
      const ulonglong2* wp=(const ulonglong2*)(g_n2T+k*128+tx8);
      ulonglong2 wA=wp[0],wB=wp[1];
      ull a[4]={pk2(av.x),pk2(av.y),pk2(av.z),pk2(av.w)};
      ull wv[4]={wA.x,wA.y,wB.x,wB.y};
      #pragma unroll
      for(int si=0;si<4;si++){
        #pragma unroll
        for(int hj=0;hj<4;hj++)ff2(acc[si][hj],a[si],wv[hj]);
      }
    }
    #pragma unroll
    for(int si=0;si<4;si++){
      int s=ty4+si;
      #pragma unroll
      for(int hp=0;hp<4;hp++){
        float2 f=up2(acc[si][hp]);
        int h=tx8+2*hp;
        H2T[h*68+s]=fmaxf(f.x+bs2[h],0.f);
        H2T[(h+1)*68+s]=fmaxf(f.y+bs2[h+1],0.f);
      }
    }
  }
  __syncthreads();
  { // 128 -> 64 + token sum
    ull acc[4][2];
    #pragma unroll
    for(int i=0;i<4;i++){acc[i][0]=0;acc[i][1]=0;}
    #pragma unroll 4
    for(int k=0;k<128;k++){
      float4 av=*(const float4*)(H2T+k*68+ty4);
      ulonglong2 wv=*(const ulonglong2*)(g_n3T+k*64+tx4);
      ull a[4]={pk2(av.x),pk2(av.y),pk2(av.z),pk2(av.w)};
      #pragma unroll
      for(int si=0;si<4;si++){ff2(acc[si][0],a[si],wv.x);ff2(acc[si][1],a[si],wv.y);}
    }
    float ps[4]={0.f,0.f,0.f,0.f};
    #pragma unroll
    for(int si=0;si<4;si++){
      float2 f0=up2(acc[si][0]),f1=up2(acc[si][1]);
      ps[0]+=fmaxf(f0.x+bs3[tx4],0.f);
      ps[1]+=fmaxf(f0.y+bs3[tx4+1],0.f);
      ps[2]+=fmaxf(f1.x+bs3[tx4+2],0.f);
      ps[3]+=fmaxf(f1.y+bs3[tx4+3],0.f);
    }
    red[ty*64+tx4]=ps[0];red[ty*64+tx4+1]=ps[1];
    red[ty*64+tx4+2]=ps[2];red[ty*64+tx4+3]=ps[3];
    __syncthreads();
    if(t<64){
      float s0=0.f;
      #pragma unroll
      for(int q=0;q<16;q++)s0+=red[q*64+t];
      g_Nsum[b*64+t]=s0;
    }
  }
}

// ---------- K6: FC head ----------
__global__ void k_head(const float* __restrict__ w1,const float* __restrict__ b1,
                       const float* __restrict__ w2,const float* __restrict__ b2,
                       const float* __restrict__ w3,const float* __restrict__ b3,
                       float* __restrict__ out){
  __shared__ float s1[1600],s2[375],s3[75],sb1[25],sb2[15],sb3[5];
  int t=threadIdx.x;
  for(int i=t;i<1600;i+=256)s1[i]=w1[i];
  for(int i=t;i<375;i+=256)s2[i]=w2[i];
  if(t<75)s3[t]=w3[t];
  if(t<25)sb1[t]=b1[t];
  if(t<15)sb2[t]=b2[t];
  if(t<5)sb3[t]=b3[t];
  __syncthreads();
  float a[64];
  #pragma unroll
  for(int j=0;j<64;j++)a[j]=g_Nsum[t*64+j];
  float h1[25];
  for(int o=0;o<25;o++){float v=sb1[o];for(int j=0;j<64;j++)v=fmaf(s1[o*64+j],a[j],v);h1[o]=v;}
  float h2[15];
  for(int o=0;o<15;o++){float v=sb2[o];for(int j=0;j<25;j++)v=fmaf(s2[o*25+j],h1[j],v);h2[o]=v;}
  for(int o=0;o<5;o++){float v=sb3[o];for(int j=0;j<15;j++)v=fmaf(s3[o*15+j],h2[j],v);out[t*5+o]=v;}
}

extern "C" void kernel_launch(void* const* d_in,const int* in_sizes,int n_in,
                              void* d_out,int out_size){
  const float* x   =(const float*)d_in[0];
  const float* gam =(const float*)d_in[3];
  const float* bet =(const float*)d_in[4];
  const float* fr1w=(const float*)d_in[5]; const float* fr1b=(const float*)d_in[6];
  const float* fr2w=(const float*)d_in[7]; const float* fr2b=(const float*)d_in[8];
  const float* fr3w=(const float*)d_in[9]; const float* fr3b=(const float*)d_in[10];
  const float* fo1w=(const float*)d_in[11];const float* fo1b=(const float*)d_in[12];
  const float* fo2w=(const float*)d_in[13];const float* fo2b=(const float*)d_in[14];
  const float* fo3w=(const float*)d_in[15];const float* fo3b=(const float*)d_in[16];
  const float* fc1w=(const float*)d_in[17];const float* fc1b=(const float*)d_in[18];
  const float* fc2w=(const float*)d_in[19];const float* fc2b=(const float*)d_in[20];
  const float* fc3w=(const float*)d_in[21];const float* fc3b=(const float*)d_in[22];
  float* out=(float*)d_out;
  int smP=(256*97+64*48)*4;
  int smN=(112*68+256*68+128*68+1024+256+128+64)*4;
  cudaFuncSetAttribute(k_prep,cudaFuncAttributeMaxDynamicSharedMemorySize,smP);
  cudaFuncSetAttribute(k_edge,cudaFuncAttributeMaxDynamicSharedMemorySize,SME_BYTES);
  cudaFuncSetAttribute(k_node,cudaFuncAttributeMaxDynamicSharedMemorySize,smN);
  k_bn<<<48,256>>>(x,gam,bet);
  k_wt<<<352,256>>>(fo1w,fo2w,fo3w,fr2w,fr3w);
  k_prep<<<256,256,smP>>>(x,fr1w,fr1b);
  k_edge<<<152,512,SME_BYTES>>>(fr2b,fr3b);
  k_node<<<256,256,smN>>>(fo1b,fo2b,fo3b);
  k_head<<<1,256>>>(fc1w,fc1b,fc2w,fc2b,fc3w,fc3b,out);
}

// round 17
// speedup vs baseline: 2.0303x; 1.2389x over previous
#include <cuda_runtime.h>
#include <cstdint>

#define BB 256
#define NN 64

typedef unsigned long long ull;

// ---------- scratch ----------
__device__ float g_scale[48], g_shift[48];
__device__ float g_xnT [BB*NN*48];     // (b,n,p)
__device__ float g_Ar  [BB*NN*256];    // (b,n,h1) includes fr1_b
__device__ float g_As  [BB*NN*256];    // (b,n,h1)
__device__ float g_EbarP[(size_t)BB*NN*128]; // (pair, half, e) partial sums
__device__ float g_Nsum[BB*64];
__device__ float g_n1T [112*256];
__device__ float g_n2T [256*128];
__device__ float g_n3T [128*64];
__device__ uint32_t g_w2h[16384];   // [128 n][128 kpair] f16x2 (rounded W2)
__device__ uint32_t g_w3h[4096];    // [64 e][64 kpair]   f16x2 (rounded W3)

__device__ __forceinline__ ull pk2(float x){ull r;asm("mov.b64 %0,{%1,%1};":"=l"(r):"f"(x));return r;}
__device__ __forceinline__ void ff2(ull&d,ull a,ull b){asm("fma.rn.f32x2 %0,%1,%2,%0;":"+l"(d):"l"(a),"l"(b));}
__device__ __forceinline__ float2 up2(ull v){float2 f;asm("mov.b64 {%0,%1},%2;":"=f"(f.x),"=f"(f.y):"l"(v));return f;}

__device__ __forceinline__ uint32_t smem_u32(const void* p){
  uint32_t a;asm("{ .reg .u64 t; cvta.to.shared.u64 t, %1; cvt.u32.u64 %0, t; }":"=r"(a):"l"(p));return a;
}
// pack 2 floats to f16x2 (lo = a, hi = b)
__device__ __forceinline__ uint32_t cvt2h(float a,float b){
  uint32_t h;asm("cvt.rn.f16x2.f32 %0, %1, %2;":"=r"(h):"f"(b),"f"(a));return h;
}
// fp32 pair -> f16x2 hi + f16x2 lo (split-A). lo captures rounding residual.
__device__ __forceinline__ void split2h(float a,float b,uint32_t&hp,uint32_t&lp){
  uint32_t h;asm("cvt.rn.f16x2.f32 %0, %1, %2;":"=r"(h):"f"(b),"f"(a));
  float ra,rb;
  asm("{.reg .b16 x,y; mov.b32 {x,y},%2; cvt.f32.f16 %0,x; cvt.f32.f16 %1,y;}"
      :"=f"(ra),"=f"(rb):"r"(h));
  uint32_t l;asm("cvt.rn.f16x2.f32 %0, %1, %2;":"=r"(l):"f"(b-rb),"f"(a-ra));
  hp=h;lp=l;
}
#define LDSM4(r0,r1,r2,r3,addr) \
  asm volatile("ldmatrix.sync.aligned.m8n8.x4.shared.b16 {%0,%1,%2,%3}, [%4];" \
    :"=r"(r0),"=r"(r1),"=r"(r2),"=r"(r3):"r"(addr))
__device__ __forceinline__ void mma_fp16(float* d,const uint32_t* a,const uint32_t* b){
  asm volatile("mma.sync.aligned.m16n8k16.row.col.f32.f16.f16.f32 "
    "{%0,%1,%2,%3},{%4,%5,%6,%7},{%8,%9},{%0,%1,%2,%3};"
    :"+f"(d[0]),"+f"(d[1]),"+f"(d[2]),"+f"(d[3])
    :"r"(a[0]),"r"(a[1]),"r"(a[2]),"r"(a[3]),"r"(b[0]),"r"(b[1]));
}
// A-operand ldmatrix address (row-major m16k16 tile), XOR-swizzled pitch P bytes
__device__ __forceinline__ uint32_t a_addr(uint32_t base,int row0,int k0,int P,int lane){
  int g=lane&7,sub=lane>>3;
  int row=row0+g+((sub&1)<<3);
  int kb=(k0+((sub>>1)<<3))*2;
  return base + row*P + (((kb>>4)^(row&7))<<4);
}
// B-operand (weights [n][k] row-major; x4 covers 2 n8k16 tiles)
__device__ __forceinline__ uint32_t b_addr(uint32_t base,int n0,int k0,int P,int lane){
  int g=lane&7,sub=lane>>3;
  int n=n0+g+((sub>>1)<<3);
  int kb=(k0+((sub&1)<<3))*2;
  return base + n*P + (((kb>>4)^(n&7))<<4);
}
#define BARG() asm volatile("bar.sync %0, 128;"::"r"(wm+1):"memory")

// k_edge smem layout (bytes)
#define O_W2H 0
#define O_W3H 65536
#define O_Z   81920    // 4 groups x 16KB (2 chunk bufs of 8KB; H2 hi/lo alias)
#define O_B2  147456
#define O_B3  147968
#define SME_BYTES 148224

// ---------- K1: BN statistics ----------
__global__ void k_bn(const float* __restrict__ x,const float* __restrict__ gam,
                     const float* __restrict__ bet){
  int p=blockIdx.x,t=threadIdx.x;
  float s=0.f,q=0.f;
  for(int i=t;i<BB*NN;i+=256){
    float v=x[(i>>6)*3072+p*64+(i&63)];
    s+=v;q+=v*v;
  }
  __shared__ float rs[256],rq[256];
  rs[t]=s;rq[t]=q;__syncthreads();
  for(int o=128;o>0;o>>=1){if(t<o){rs[t]+=rs[t+o];rq[t]+=rq[t+o];}__syncthreads();}
  if(t==0){
    float m=rs[0]*(1.f/16384.f);
    float var=rq[0]*(1.f/16384.f)-m*m;
    float sc=gam[p]*rsqrtf(var+1e-5f);
    g_scale[p]=sc;g_shift[p]=bet[p]-m*sc;
  }
}

// ---------- K2: weight prep ----------
__global__ void k_wt(const float* __restrict__ w1,const float* __restrict__ w2,
                     const float* __restrict__ w3,const float* __restrict__ fr2w,
                     const float* __restrict__ fr3w){
  int i=blockIdx.x*256+threadIdx.x;
  if(i<28672){int k=i>>8,h=i&255;g_n1T[i]=w1[h*112+k];}
  else if(i<61440){int j=i-28672,k=j>>7,h=j&127;g_n2T[j]=w2[h*256+k];}
  else if(i<69632){int j=i-61440,k=j>>6,e=j&63;g_n3T[j]=w3[e*128+k];}
  else if(i<86016){
    int j=i-69632,n=j>>7,cp=j&127;
    g_w2h[j]=cvt2h(fr2w[n*256+2*cp],fr2w[n*256+2*cp+1]);
  }else if(i<90112){
    int j=i-86016,e=j>>6,cp=j&63;
    g_w3h[j]=cvt2h(fr3w[e*128+2*cp],fr3w[e*128+2*cp+1]);
  }
}

// ---------- K3: xn + per-node edge pre-GEMM Ar(+b1)/As ----------
__global__ __launch_bounds__(256,1) void k_prep(const float* __restrict__ x,
                                                const float* __restrict__ w1,
                                                const float* __restrict__ b1){
  extern __shared__ float sm[];
  float* W=sm;          // [256][97]
  float* xs=W+256*97;   // [64][48]
  int t=threadIdx.x,b=blockIdx.x;
  for(int i=t;i<256*96;i+=256){int o=i/96,k=i-o*96;W[o*97+k]=w1[i];}
  for(int i=t;i<48*64;i+=256){
    int p=i>>6,n=i&63;
    float v=x[b*3072+i]*g_scale[p]+g_shift[p];
    xs[n*48+p]=v;
    g_xnT[(b*64+n)*48+p]=v;
  }
  __syncthreads();
  int o=t;
  float bb=b1[o];
  for(int nt=0;nt<64;nt+=16){
    float aR[16],aS[16];
    #pragma unroll
    for(int j=0;j<16;j++){aR[j]=bb;aS[j]=0.f;}
    for(int p=0;p<48;p++){
      float wr=W[o*97+p],ws=W[o*97+48+p];
      #pragma unroll
      for(int j=0;j<16;j++){
        float xv=xs[(nt+j)*48+p];
        aR[j]=fmaf(wr,xv,aR[j]);aS[j]=fmaf(ws,xv,aS[j]);
      }
    }
    #pragma unroll
    for(int j=0;j<16;j++){
      g_Ar[(b*64+nt+j)*256+o]=aR[j];
      g_As[(b*64+nt+j)*256+o]=aS[j];
    }
  }
}

// ---------- K4: edge MLP via mma.sync fp16 split-A / rounded-B (2 passes) ----------
// wm = w>>2: each SMSP hosts one warp of each group (R13 win).
// Fill of chunk c+1 pipelined (R16). A = Z1/H2 split fp16 hi+lo (near-exact);
// B = W2/W3 rounded to fp16 (err ~2^-12.8) -> 2 MMA passes instead of 3.
__global__ __launch_bounds__(512,1) void k_edge(const float* __restrict__ b2,
                                                const float* __restrict__ b3){
  extern __shared__ char smc[];
  uint32_t sb=smem_u32(smc);
  float* b2s=(float*)(smc+O_B2);
  float* b3s=(float*)(smc+O_B3);
  int t=threadIdx.x,lane=t&31,w=t>>5;
  int wm=w>>2,wn=w&3;           // wm: row group (32 rows), wn: col group
  int gt=wn*32+lane;            // 0..127 within wm group
  int g=lane>>2,tt=lane&3;
  // stage W2/W3 (fp16) into swizzled smem
  for(int i=t;i<16384;i+=512){
    int n=i>>7,cp=i&127;
    uint32_t off=n*512u+(((cp>>2)^(n&7))<<4)+((cp&3)<<2);
    *(uint32_t*)(smc+O_W2H+off)=g_w2h[i];
  }
  for(int i=t;i<4096;i+=512){
    int e=i>>6,cp=i&63;
    uint32_t off=e*256u+(((cp>>2)^(e&7))<<4)+((cp&3)<<2);
    *(uint32_t*)(smc+O_W3H+off)=g_w3h[i];
  }
  if(t<128)b2s[t]=b2[t];
  if(t>=128&&t<192)b3s[t-128]=b3[t-128];
  __syncthreads();

  char* zgrp=smc+O_Z+wm*16384;
  uint32_t zgrp_u=sb+O_Z+wm*16384;

  // fill-pipe invariants
  int cpF=gt&31;                 // jj-invariant k pair index
  int rlb=gt>>5;                 // jj row base (rl = rlb + 4*jj)
  int phF=wm>>1;                 // jj-invariant Ar row

  for(int base=blockIdx.x*2;base<BB*NN;base+=2*gridDim.x){
    int b=base>>6;
    const float* ArB=g_Ar+(size_t)base*256;
    const float* AsB=g_As+(size_t)b*16384;
    float acc[2][4][4];
    #pragma unroll
    for(int m=0;m<2;m++)
      #pragma unroll
      for(int n=0;n<4;n++){acc[m][n][0]=0.f;acc[m][n][1]=0.f;acc[m][n][2]=0.f;acc[m][n][3]=0.f;}

    // full fill of chunk c into buf d (used for chunk 0 only)
    #define FILLZ(c,d) do{ \
      char* zh=zgrp+(d)*8192; char* zl=zh+4096; \
      int kk=((c)<<6)+(cpF<<1); \
      float2 arv=*(const float2*)(ArB+phF*256+kk); \
      _Pragma("unroll") \
      for(int jj=0;jj<8;jj++){ \
        int rl=rlb+(jj<<2); \
        int s=(wm*32+rl)&63; \
        float2 as=*(const float2*)(AsB+s*256+kk); \
        uint32_t h,l;split2h(fmaxf(arv.x+as.x,0.f),fmaxf(arv.y+as.y,0.f),h,l); \
        uint32_t off=rl*128u+(((cpF>>2)^(rl&7))<<4)+((cpF&3)<<2); \
        *(uint32_t*)(zh+off)=h;*(uint32_t*)(zl+off)=l; \
      } \
    }while(0)
    // consume 4 prefetched as values (jj = j0..j0+3) into buf d
    #define CONSUME4(d,j0) do{ \
      char* zh=zgrp+(d)*8192; char* zl=zh+4096; \
      _Pragma("unroll") \
      for(int j=0;j<4;j++){ \
        int rl=rlb+(((j0)+j)<<2); \
        uint32_t h,l;split2h(fmaxf(arP.x+asP[j].x,0.f),fmaxf(arP.y+asP[j].y,0.f),h,l); \
        uint32_t off=rl*128u+(((cpF>>2)^(rl&7))<<4)+((cpF&3)<<2); \
        *(uint32_t*)(zh+off)=h;*(uint32_t*)(zl+off)=l; \
      } \
    }while(0)
    // prefetch 4 as values for chunk cc, jj=j0..j0+3
    #define PREF4(cc,j0) do{ \
      int kk=((cc)<<6)+(cpF<<1); \
      _Pragma("unroll") \
      for(int j=0;j<4;j++){ \
        int rl=rlb+(((j0)+j)<<2); \
        int s=(wm*32+rl)&63; \
        asP[j]=*(const float2*)(AsB+s*256+kk); \
      } \
    }while(0)

    FILLZ(0,0);
    BARG();
    float2 arP; float2 asP[4];
    #pragma unroll 1
    for(int c=0;c<4;c++){
      uint32_t zb=zgrp_u+(c&1)*8192;
      if(c<3){
        int kk=((c+1)<<6)+(cpF<<1);
        arP=*(const float2*)(ArB+phF*256+kk);
        PREF4(c+1,0);
      }
      #pragma unroll 1
      for(int ks=0;ks<4;ks++){
        int kg=(c<<6)+(ks<<4);
        uint32_t bh[4][2];
        #pragma unroll
        for(int p=0;p<2;p++){
          uint32_t r0,r1,r2,r3;
          LDSM4(r0,r1,r2,r3,b_addr(sb+O_W2H,wn*32+p*16,kg,512,lane));
          bh[2*p][0]=r0;bh[2*p][1]=r1;bh[2*p+1][0]=r2;bh[2*p+1][1]=r3;
        }
        uint32_t ah[2][4],al[2][4];
        #pragma unroll
        for(int m=0;m<2;m++){
          LDSM4(ah[m][0],ah[m][1],ah[m][2],ah[m][3],a_addr(zb,m*16,ks*16,128,lane));
          LDSM4(al[m][0],al[m][1],al[m][2],al[m][3],a_addr(zb+4096,m*16,ks*16,128,lane));
        }
        #pragma unroll
        for(int m=0;m<2;m++)
          #pragma unroll
          for(int n=0;n<4;n++)mma_fp16(acc[m][n],ah[m],bh[n]);
        #pragma unroll
        for(int m=0;m<2;m++)
          #pragma unroll
          for(int n=0;n<4;n++)mma_fp16(acc[m][n],al[m],bh[n]);
        if(c<3&&ks==1){
          CONSUME4((c+1)&1,0);
          PREF4(c+1,4);
        }
      }
      if(c<3)CONSUME4((c+1)&1,4);
      BARG();
    }
    // ---- epilogue1: acc -> relu(+b2) -> H2 hi/lo (aliases Z region) ----
    #pragma unroll
    for(int m=0;m<2;m++){
      int r0=m*16+g;
      #pragma unroll
      for(int n=0;n<4;n++){
        int c0=wn*32+n*8+tt*2;
        float f0=fmaxf(acc[m][n][0]+b2s[c0],0.f);
        float f1=fmaxf(acc[m][n][1]+b2s[c0+1],0.f);
        float f2=fmaxf(acc[m][n][2]+b2s[c0],0.f);
        float f3=fmaxf(acc[m][n][3]+b2s[c0+1],0.f);
        uint32_t h0,l0,h1,l1;split2h(f0,f1,h0,l0);split2h(f2,f3,h1,l1);
        uint32_t cb=(uint32_t)(c0<<1);
        int r8=r0+8;
        uint32_t off0=r0*256u+(((cb>>4)^(r0&7))<<4)+(cb&15);
        uint32_t off1=r8*256u+(((cb>>4)^(r8&7))<<4)+(cb&15);
        *(uint32_t*)(zgrp+off0)=h0;*(uint32_t*)(zgrp+8192+off0)=l0;
        *(uint32_t*)(zgrp+off1)=h1;*(uint32_t*)(zgrp+8192+off1)=l1;
      }
    }
    BARG();
    // ---- GEMM3: D3(32x64 per wm) = H2(32x128) * W3^T ----
    float a3[2][2][4];
    #pragma unroll
    for(int m=0;m<2;m++)
      #pragma unroll
      for(int n=0;n<2;n++){a3[m][n][0]=0.f;a3[m][n][1]=0.f;a3[m][n][2]=0.f;a3[m][n][3]=0.f;}
    #pragma unroll 1
    for(int ks=0;ks<8;ks++){
      uint32_t bh[2][2];
      {
        uint32_t r0,r1,r2,r3;
        LDSM4(r0,r1,r2,r3,b_addr(sb+O_W3H,wn*16,ks*16,256,lane));
        bh[0][0]=r0;bh[0][1]=r1;bh[1][0]=r2;bh[1][1]=r3;
      }
      uint32_t ah[2][4],al[2][4];
      #pragma unroll
      for(int m=0;m<2;m++){
        LDSM4(ah[m][0],ah[m][1],ah[m][2],ah[m][3],a_addr(zgrp_u,m*16,ks*16,256,lane));
        LDSM4(al[m][0],al[m][1],al[m][2],al[m][3],a_addr(zgrp_u+8192,m*16,ks*16,256,lane));
      }
      #pragma unroll
      for(int m=0;m<2;m++)
        #pragma unroll
        for(int n=0;n<2;n++){
          mma_fp16(a3[m][n],ah[m],bh[n]);
          mma_fp16(a3[m][n],al[m],bh[n]);
        }
    }
    // ---- epilogue2: relu(+b3), mask s==r, reduce over rows -> global partials ----
    int php=wm>>1;
    {
      int r=(base+php)&63;
      float ps[2][2];
      #pragma unroll
      for(int n=0;n<2;n++){ps[n][0]=0.f;ps[n][1]=0.f;}
      #pragma unroll
      for(int m=0;m<2;m++){
        int row=wm*32+m*16+g;
        float m1=((row&63)!=r)?1.f:0.f;
        float m2=(((row+8)&63)!=r)?1.f:0.f;
        #pragma unroll
        for(int n=0;n<2;n++){
          int c0=wn*16+n*8+tt*2;
          ps[n][0]+=m1*fmaxf(a3[m][n][0]+b3s[c0],0.f)+m2*fmaxf(a3[m][n][2]+b3s[c0],0.f);
          ps[n][1]+=m1*fmaxf(a3[m][n][1]+b3s[c0+1],0.f)+m2*fmaxf(a3[m][n][3]+b3s[c0+1],0.f);
        }
      }
      #pragma unroll
      for(int n=0;n<2;n++)
        #pragma unroll
        for(int q=0;q<2;q++){
          float v=ps[n][q];
          v+=__shfl_xor_sync(0xFFFFFFFFu,v,4);
          v+=__shfl_xor_sync(0xFFFFFFFFu,v,8);
          v+=__shfl_xor_sync(0xFFFFFFFFu,v,16);
          ps[n][q]=v;
        }
      if(g==0){
        float* dst=g_EbarP+((size_t)(base+php)*128+(size_t)(wm&1)*64);
        #pragma unroll
        for(int n=0;n<2;n++){
          int c0=wn*16+n*8+tt*2;
          dst[c0]=ps[n][0];
          dst[c0+1]=ps[n][1];
        }
      }
    }
    BARG();     // zgrp free for next iteration's fill
    #undef FILLZ
    #undef CONSUME4
    #undef PREF4
  }
}

// ---------- K5: node MLP + per-batch sum ----------
__global__ __launch_bounds__(256,1) void k_node(const float* __restrict__ bo1,
    const float* __restrict__ bo2,const float* __restrict__ bo3){
  extern __shared__ float sm[];
  float* CT=sm;             // [112][68]
  float* H1T=CT+112*68;     // [256][68]
  float* H2T=H1T+256*68;    // [128][68]
  float* red=H2T+128*68;    // [16][64]
  float* bs1=red+1024;float* bs2=bs1+256;float* bs3=bs2+128;
  int t=threadIdx.x,b=blockIdx.x;
  int ty=t>>4,tx=t&15,ty4=ty*4,tx8=tx*8,tx4=tx*4,tx16=tx*16;
  bs1[t]=bo1[t];
  if(t<128)bs2[t]=bo2[t];
  if(t<64)bs3[t]=bo3[t];
  for(int i=t;i<64*48;i+=256){int n=i/48,p=i-n*48;CT[p*68+n]=g_xnT[(b*64+n)*48+p];}
  for(int i=t;i<64*64;i+=256){
    int n=i>>6,e=i&63;
    const float* pp=g_EbarP+((size_t)(b*64+n)*128);
    CT[(48+e)*68+n]=pp[e]+pp[64+e];
  }
  __syncthreads();
  { // 112 -> 256
    ull acc[4][8];
    #pragma unroll
    for(int i=0;i<4;i++)
      #pragma unroll
      for(int j=0;j<8;j++)acc[i][j]=0;
    #pragma unroll 4
    for(int k=0;k<112;k++){
      float4 av=*(const float4*)(CT+k*68+ty4);
      const ulonglong2* wp=(const ulonglong2*)(g_n1T+k*256+tx16);
      ulonglong2 w0=wp[0],w1=wp[1],w2=wp[2],w3=wp[3];
      ull a[4]={pk2(av.x),pk2(av.y),pk2(av.z),pk2(av.w)};
      #pragma unroll
      for(int si=0;si<4;si++){
        ff2(acc[si][0],a[si],w0.x);ff2(acc[si][1],a[si],w0.y);
        ff2(acc[si][2],a[si],w1.x);ff2(acc[si][3],a[si],w1.y);
        ff2(acc[si][4],a[si],w2.x);ff2(acc[si][5],a[si],w2.y);
        ff2(acc[si][6],a[si],w3.x);ff2(acc[si][7],a[si],w3.y);
      }
    }
    #pragma unroll
    for(int si=0;si<4;si++){
      int s=ty4+si;
      #pragma unroll
      for(int hp=0;hp<8;hp++){
        float2 f=up2(acc[si][hp]);
        int h=tx16+2*hp;
        H1T[h*68+s]=fmaxf(f.x+bs1[h],0.f);
        H1T[(h+1)*68+s]=fmaxf(f.y+bs1[h+1],0.f);
      }
    }
  }
  __syncthreads();
  { // 256 -> 128
    ull acc[4][4];
    #pragma unroll
    for(int i=0;i<4;i++){acc[i][0]=0;acc[i][1]=0;acc[i][2]=0;acc[i][3]=0;}
    #pragma unroll 4
    for(int k=0;k<256;k++){
      float4 av=*(const float4*)(H1T+k*68+ty4);
      const ulonglong2* wp=(const ulonglong2*)(g_n2T+k*128+tx8);
      ulonglong2 wA=wp[0],wB=wp[1];
      ull a[4]={pk2(av.x),pk2(av.y),pk2(av.z),pk2(av.w)};
      ull wv[4]={wA.x,wA.y,wB.x,wB.y};
      #pragma unroll
      for(int si=0;si<4;si++){
        #pragma unroll
        for(int hj=0;hj<4;hj++)ff2(acc[si][hj],a[si],wv[hj]);
      }
    }
    #pragma unroll
    for(int si=0;si<4;si++){
      int s=ty4+si;
      #pragma unroll
      for(int hp=0;hp<4;hp++){
        float2 f=up2(acc[si][hp]);
        int h=tx8+2*hp;
        H2T[h*68+s]=fmaxf(f.x+bs2[h],0.f);
        H2T[(h+1)*68+s]=fmaxf(f.y+bs2[h+1],0.f);
      }
    }
  }
  __syncthreads();
  { // 128 -> 64 + token sum
    ull acc[4][2];
    #pragma unroll
    for(int i=0;i<4;i++){acc[i][0]=0;acc[i][1]=0;}
    #pragma unroll 4
    for(int k=0;k<128;k++){
      float4 av=*(const float4*)(H2T+k*68+ty4);
      ulonglong2 wv=*(const ulonglong2*)(g_n3T+k*64+tx4);
      ull a[4]={pk2(av.x),pk2(av.y),pk2(av.z),pk2(av.w)};
      #pragma unroll
      for(int si=0;si<4;si++){ff2(acc[si][0],a[si],wv.x);ff2(acc[si][1],a[si],wv.y);}
    }
    float ps[4]={0.f,0.f,0.f,0.f};
    #pragma unroll
    for(int si=0;si<4;si++){
      float2 f0=up2(acc[si][0]),f1=up2(acc[si][1]);
      ps[0]+=fmaxf(f0.x+bs3[tx4],0.f);
      ps[1]+=fmaxf(f0.y+bs3[tx4+1],0.f);
      ps[2]+=fmaxf(f1.x+bs3[tx4+2],0.f);
      ps[3]+=fmaxf(f1.y+bs3[tx4+3],0.f);
    }
    red[ty*64+tx4]=ps[0];red[ty*64+tx4+1]=ps[1];
    red[ty*64+tx4+2]=ps[2];red[ty*64+tx4+3]=ps[3];
    __syncthreads();
    if(t<64){
      float s0=0.f;
      #pragma unroll
      for(int q=0;q<16;q++)s0+=red[q*64+t];
      g_Nsum[b*64+t]=s0;
    }
  }
}

// ---------- K6: FC head ----------
__global__ void k_head(const float* __restrict__ w1,const float* __restrict__ b1,
                       const float* __restrict__ w2,const float* __restrict__ b2,
                       const float* __restrict__ w3,const float* __restrict__ b3,
                       float* __restrict__ out){
  __shared__ float s1[1600],s2[375],s3[75],sb1[25],sb2[15],sb3[5];
  int t=threadIdx.x;
  for(int i=t;i<1600;i+=256)s1[i]=w1[i];
  for(int i=t;i<375;i+=256)s2[i]=w2[i];
  if(t<75)s3[t]=w3[t];
  if(t<25)sb1[t]=b1[t];
  if(t<15)sb2[t]=b2[t];
  if(t<5)sb3[t]=b3[t];
  __syncthreads();
  float a[64];
  #pragma unroll
  for(int j=0;j<64;j++)a[j]=g_Nsum[t*64+j];
  float h1[25];
  for(int o=0;o<25;o++){float v=sb1[o];for(int j=0;j<64;j++)v=fmaf(s1[o*64+j],a[j],v);h1[o]=v;}
  float h2[15];
  for(int o=0;o<15;o++){float v=sb2[o];for(int j=0;j<25;j++)v=fmaf(s2[o*25+j],h1[j],v);h2[o]=v;}
  for(int o=0;o<5;o++){float v=sb3[o];for(int j=0;j<15;j++)v=fmaf(s3[o*15+j],h2[j],v);out[t*5+o]=v;}
}

extern "C" void kernel_launch(void* const* d_in,const int* in_sizes,int n_in,
                              void* d_out,int out_size){
  const float* x   =(const float*)d_in[0];
  const float* gam =(const float*)d_in[3];
  const float* bet =(const float*)d_in[4];
  const float* fr1w=(const float*)d_in[5]; const float* fr1b=(const float*)d_in[6];
  const float* fr2w=(const float*)d_in[7]; const float* fr2b=(const float*)d_in[8];
  const float* fr3w=(const float*)d_in[9]; const float* fr3b=(const float*)d_in[10];
  const float* fo1w=(const float*)d_in[11];const float* fo1b=(const float*)d_in[12];
  const float* fo2w=(const float*)d_in[13];const float* fo2b=(const float*)d_in[14];
  const float* fo3w=(const float*)d_in[15];const float* fo3b=(const float*)d_in[16];
  const float* fc1w=(const float*)d_in[17];const float* fc1b=(const float*)d_in[18];
  const float* fc2w=(const float*)d_in[19];const float* fc2b=(const float*)d_in[20];
  const float* fc3w=(const float*)d_in[21];const float* fc3b=(const float*)d_in[22];
  float* out=(float*)d_out;
  int smP=(256*97+64*48)*4;
  int smN=(112*68+256*68+128*68+1024+256+128+64)*4;
  cudaFuncSetAttribute(k_prep,cudaFuncAttributeMaxDynamicSharedMemorySize,smP);
  cudaFuncSetAttribute(k_edge,cudaFuncAttributeMaxDynamicSharedMemorySize,SME_BYTES);
  cudaFuncSetAttribute(k_node,cudaFuncAttributeMaxDynamicSharedMemorySize,smN);
  k_bn<<<48,256>>>(x,gam,bet);
  k_wt<<<352,256>>>(fo1w,fo2w,fo3w,fr2w,fr3w);
  k_prep<<<256,256,smP>>>(x,fr1w,fr1b);
  k_edge<<<152,512,SME_BYTES>>>(fr2b,fr3b);
  k_node<<<256,256,smN>>>(fo1b,fo2b,fo3b);
  k_head<<<1,256>>>(fc1w,fc1b,fc2w,fc2b,fc3w,fc3b,out);
}